// round 7
// baseline (speedup 1.0000x reference)
#include <cuda_runtime.h>

#define TB 8192   // batch
#define TT 512    // seq len
#define DD 8      // input size
#define HH 64     // hidden
#define RP 36     // row stride (floats): 144B, bank-stride 4 -> conflict-free f4 ops
#define NT 128    // threads: 2 warp-pairs; pair rg owns 16 rows, u = tid&63

// Gate-interleaved transposed weights WTg[k][u][gate] + interleaved biases.
#define WT_TOTAL 185856
__device__ float g_wt[WT_TOTAL];

struct WSrcs { const float* p[18]; };
__constant__ int c_woff[19] = {0, 2048, 18432, 34816, 51200, 67584, 83968,
                               102400, 118784, 135168, 151552, 167936, 184320,
                               184576, 184832, 185088, 185344, 185600, 185856};

__global__ void transpose_all(WSrcs ws) {
    int idx = blockIdx.x * blockDim.x + threadIdx.x;
    if (idx >= WT_TOTAL) return;
    int seg = 0;
    #pragma unroll
    for (int i = 1; i < 18; i++) seg += (idx >= c_woff[i]);
    int off  = c_woff[seg];
    int cols = (c_woff[seg + 1] - off) >> 8;
    int pos = idx - off;
    int k = pos >> 8, rem = pos & 255, u = rem >> 2, g = rem & 3;
    g_wt[idx] = ws.p[seg][(g * HH + u) * cols + k];
}

__device__ __forceinline__ float tanh_fast(float x) {
    float y;
    asm("tanh.approx.f32 %0, %1;" : "=f"(y) : "f"(x));
    return y;
}
__device__ __forceinline__ float sig_fast(float x) {
    return fmaf(0.5f, tanh_fast(0.5f * x), 0.5f);
}

typedef unsigned long long ull;
__device__ __forceinline__ ull pack2(float w) {
    ull p; asm("mov.b64 %0, {%1, %1};" : "=l"(p) : "f"(w)); return p;
}
__device__ __forceinline__ void fma2(ull& acc, ull a, ull b) {
    asm("fma.rn.f32x2 %0, %1, %2, %0;" : "+l"(acc) : "l"(a), "l"(b));
}
__device__ __forceinline__ void unpack2(ull p, float& lo, float& hi) {
    asm("mov.b64 {%0, %1}, %2;" : "=f"(lo), "=f"(hi) : "l"(p));
}

// warp-pair barrier: pair rg = warps {2rg, 2rg+1}, 64 threads, named ids 1..2
__device__ __forceinline__ void pair_bar(int rg) {
    asm volatile("bar.sync %0, 64;" :: "r"(rg + 1) : "memory");
}

// acc[g*8+q] += WTg[k][u][g] * buf[k][rg*16 + 2q..2q+1]; 16 rows per thread.
__device__ __forceinline__ void gemv8(ull acc[32], const float* __restrict__ WTg,
                                      int K, const float* __restrict__ buf,
                                      int u, int rg) {
    const float* bp = buf + rg * 16;
    #pragma unroll 4
    for (int k = 0; k < K; k++) {
        float4 w4 = *(const float4*)(WTg + k * 256 + u * 4);   // 512B/warp LDG.128
        ull wi = pack2(w4.x), wf = pack2(w4.y);
        ull wg = pack2(w4.z), wo = pack2(w4.w);
        const ulonglong2* xp = (const ulonglong2*)(bp + k * RP);
        ulonglong2 va = xp[0], vb = xp[1], vc = xp[2], vd = xp[3];  // broadcasts
        fma2(acc[0],  wi, va.x); fma2(acc[1],  wi, va.y);
        fma2(acc[2],  wi, vb.x); fma2(acc[3],  wi, vb.y);
        fma2(acc[4],  wi, vc.x); fma2(acc[5],  wi, vc.y);
        fma2(acc[6],  wi, vd.x); fma2(acc[7],  wi, vd.y);
        fma2(acc[8],  wf, va.x); fma2(acc[9],  wf, va.y);
        fma2(acc[10], wf, vb.x); fma2(acc[11], wf, vb.y);
        fma2(acc[12], wf, vc.x); fma2(acc[13], wf, vc.y);
        fma2(acc[14], wf, vd.x); fma2(acc[15], wf, vd.y);
        fma2(acc[16], wg, va.x); fma2(acc[17], wg, va.y);
        fma2(acc[18], wg, vb.x); fma2(acc[19], wg, vb.y);
        fma2(acc[20], wg, vc.x); fma2(acc[21], wg, vc.y);
        fma2(acc[22], wg, vd.x); fma2(acc[23], wg, vd.y);
        fma2(acc[24], wo, va.x); fma2(acc[25], wo, va.y);
        fma2(acc[26], wo, vb.x); fma2(acc[27], wo, vb.y);
        fma2(acc[28], wo, vc.x); fma2(acc[29], wo, vc.y);
        fma2(acc[30], wo, vd.x); fma2(acc[31], wo, vd.y);
    }
}

// One LSTM layer step for 16 rows/thread. read_bar: needed when hout is also
// in the gemv read set (single-buffered h0/h1); h2 is double-buffered -> false.
__device__ __forceinline__ void layer16(const float* __restrict__ WTi, int Ki,
                                        const float* __restrict__ in1,
                                        const float* __restrict__ WTi2,
                                        const float* __restrict__ in2,
                                        const float* __restrict__ WTh,
                                        const float* __restrict__ hprev,
                                        const float* __restrict__ Bint,
                                        float* __restrict__ cbuf,
                                        float* __restrict__ hout,
                                        bool read_bar, int u, int rg) {
    ull acc[32];
    {
        float4 b4 = *(const float4*)(Bint + u * 4);
        ull bi = pack2(b4.x), bf = pack2(b4.y), bg = pack2(b4.z), bo = pack2(b4.w);
        #pragma unroll
        for (int q = 0; q < 8; q++) {
            acc[q] = bi; acc[8 + q] = bf; acc[16 + q] = bg; acc[24 + q] = bo;
        }
    }
    gemv8(acc, WTi, Ki, in1, u, rg);
    if (in2) gemv8(acc, WTi2, HH, in2, u, rg);
    gemv8(acc, WTh, HH, hprev, u, rg);
    if (read_bar) pair_bar(rg);           // all pair reads of hout done

    float* cb = cbuf + u * RP + rg * 16;
    float* hb = hout + u * RP + rg * 16;
    #pragma unroll
    for (int qq = 0; qq < 4; qq++) {
        float4 cv = *(float4*)(cb + 4 * qq);
        int q0 = 2 * qq, q1 = 2 * qq + 1;
        float i0, i1, f0, f1, g0, g1, o0, o1;
        float4 hv;
        unpack2(acc[q0],      i0, i1);
        unpack2(acc[8 + q0],  f0, f1);
        unpack2(acc[16 + q0], g0, g1);
        unpack2(acc[24 + q0], o0, o1);
        cv.x = sig_fast(f0) * cv.x + sig_fast(i0) * tanh_fast(g0);
        hv.x = sig_fast(o0) * tanh_fast(cv.x);
        cv.y = sig_fast(f1) * cv.y + sig_fast(i1) * tanh_fast(g1);
        hv.y = sig_fast(o1) * tanh_fast(cv.y);
        unpack2(acc[q1],      i0, i1);
        unpack2(acc[8 + q1],  f0, f1);
        unpack2(acc[16 + q1], g0, g1);
        unpack2(acc[24 + q1], o0, o1);
        cv.z = sig_fast(f0) * cv.z + sig_fast(i0) * tanh_fast(g0);
        hv.z = sig_fast(o0) * tanh_fast(cv.z);
        cv.w = sig_fast(f1) * cv.w + sig_fast(i1) * tanh_fast(g1);
        hv.w = sig_fast(o1) * tanh_fast(cv.w);
        *(float4*)(cb + 4 * qq) = cv;
        *(float4*)(hb + 4 * qq) = hv;
    }
    pair_bar(rg);                          // h visible to pair
}

#define LSZ (HH * RP)   // 2304 floats per [64][RP] buffer

__global__ __launch_bounds__(NT, 3)
void lstm_main(const float* __restrict__ enc_x, const float* __restrict__ dec_x,
               const float* __restrict__ fcW, const float* __restrict__ fcb,
               float* __restrict__ out) {
    extern __shared__ float sm[];
    float* s_h0 = sm;                 // [64][RP]
    float* s_h1 = sm + LSZ;           // [64][RP]
    float* s_h2 = sm + 2 * LSZ;       // [2 parity][64][RP]
    float* s_c  = sm + 4 * LSZ;       // [3 layer][64][RP]
    float* s_x  = sm + 7 * LSZ;       // [2 parity][8][RP]
    float* s_fc = s_x + 2 * DD * RP;  // 512 fcW^T + 8 fcb

    int tid = threadIdx.x;
    int bid = blockIdx.x;
    int rg  = tid >> 6;               // pair id (16 rows each)
    int t6  = tid & 63;
    int u   = t6;                     // hidden unit

    // 512 groups of 16 rows on 444 CTAs: bid<68 -> 2 groups, else 1.
    int ng, g0;
    if (bid < 68) { ng = 2; g0 = 2 * bid; }
    else          { ng = 1; g0 = bid + 68; }
    int b0 = g0 * 16;

    // init (all 128 threads; single block-wide sync, then inactive pairs exit)
    for (int i = tid; i < 7 * LSZ; i += NT) sm[i] = 0.f;
    for (int i = tid; i < DD * HH; i += NT) {
        int uu = i >> 3, d = i & 7;
        s_fc[uu * 8 + d] = fcW[d * HH + uu];
    }
    if (tid < DD) s_fc[512 + tid] = fcb[tid];
    __syncthreads();
    if (rg >= ng) return;

    const float* WT_e0i = g_wt;           const float* WT_e0h = g_wt + 2048;
    const float* WT_e1i = g_wt + 18432;   const float* WT_e1h = g_wt + 34816;
    const float* WT_e2i = g_wt + 51200;   const float* WT_e2h = g_wt + 67584;
    const float* WT_d0i = g_wt + 83968;   const float* WT_d0h = g_wt + 102400;
    const float* WT_d1i = g_wt + 118784;  const float* WT_d1h = g_wt + 135168;
    const float* WT_d2i = g_wt + 151552;  const float* WT_d2h = g_wt + 167936;
    const float* B_e0 = g_wt + 184320;    const float* B_e1 = g_wt + 184576;
    const float* B_e2 = g_wt + 184832;    const float* B_d0 = g_wt + 185088;
    const float* B_d1 = g_wt + 185344;    const float* B_d2 = g_wt + 185600;

    int xrl = rg * 16 + (t6 >> 3);        // local rows xrl, xrl+8
    int xk  = t6 & 7;
    const size_t xb1 = (size_t)(b0 + xrl) * TT * DD + xk;
    const size_t xb2 = xb1 + (size_t)8 * TT * DD;

    // prologue: x(t=0) into parity 0
    s_x[xk * RP + xrl]     = enc_x[xb1];
    s_x[xk * RP + xrl + 8] = enc_x[xb2];
    pair_bar(rg);

    // ---------------- encoder ----------------
    for (int t = 0; t < TT; t++) {
        int p = t & 1;
        const float* sx = s_x + p * DD * RP;
        float xa, xb;
        if (t < TT - 1) { xa = enc_x[xb1 + (size_t)(t + 1) * DD]; xb = enc_x[xb2 + (size_t)(t + 1) * DD]; }
        else            { xa = dec_x[xb1];                        xb = dec_x[xb2]; }
        layer16(WT_e0i, DD, sx, nullptr, nullptr, WT_e0h, s_h0, B_e0, s_c,           s_h0, true,  u, rg);
        {   // stage next-step x into other parity (own slot; ordered by pair bars)
            float* xo = s_x + (p ^ 1) * DD * RP;
            xo[xk * RP + xrl] = xa; xo[xk * RP + xrl + 8] = xb;
        }
        layer16(WT_e1i, HH, s_h0, nullptr, nullptr, WT_e1h, s_h1, B_e1, s_c + LSZ,     s_h1, true,  u, rg);
        layer16(WT_e2i, HH, s_h1, nullptr, nullptr, WT_e2h, s_h2 + (p ^ 1) * LSZ, B_e2, s_c + 2 * LSZ, s_h2 + p * LSZ, false, u, rg);
    }

    // ---------------- decoder ----------------
    for (int t = 0; t < TT; t++) {
        int p = t & 1;
        const float* sx = s_x + p * DD * RP;
        int tn = (t + 1 < TT) ? t + 1 : t;
        float xa = dec_x[xb1 + (size_t)tn * DD];
        float xb = dec_x[xb2 + (size_t)tn * DD];
        const float* ybuf = (t > 0) ? (s_h2 + (p ^ 1) * LSZ) : nullptr;   // y_prev
        layer16(WT_d0i, DD, sx, WT_d0i + DD * 256, ybuf, WT_d0h, s_h0, B_d0, s_c,           s_h0, true,  u, rg);
        {
            float* xo = s_x + (p ^ 1) * DD * RP;
            xo[xk * RP + xrl] = xa; xo[xk * RP + xrl + 8] = xb;
        }
        layer16(WT_d1i, HH, s_h0, nullptr, nullptr, WT_d1h, s_h1, B_d1, s_c + LSZ,     s_h1, true,  u, rg);
        layer16(WT_d2i, HH, s_h1, nullptr, nullptr, WT_d2h, s_h2 + (p ^ 1) * LSZ, B_d2, s_c + 2 * LSZ, s_h2 + p * LSZ, false, u, rg);

        // pred = h2 @ fcW^T + fcb for rows xrl, xrl+8 (ordered by L2's pair bar)
        const float* h2 = s_h2 + p * LSZ;
        float a1 = s_fc[512 + xk], a2 = a1;
        #pragma unroll 8
        for (int uu = 0; uu < HH; uu++) {
            float w = s_fc[uu * 8 + xk];
            a1 = fmaf(w, h2[uu * RP + xrl], a1);
            a2 = fmaf(w, h2[uu * RP + xrl + 8], a2);
        }
        out[(size_t)(b0 + xrl) * TT * DD + t * DD + xk] = a1;
        out[(size_t)(b0 + xrl + 8) * TT * DD + t * DD + xk] = a2;
    }
}

extern "C" void kernel_launch(void* const* d_in, const int* in_sizes, int n_in,
                              void* d_out, int out_size) {
    const float* enc_x = (const float*)d_in[0];
    const float* dec_x = (const float*)d_in[1];

    WSrcs ws;
    const int src_idx[18] = {2, 3, 5, 6, 8, 9, 11, 12, 14, 15, 17, 18,
                             4, 7, 10, 13, 16, 19};
    for (int i = 0; i < 18; i++) ws.p[i] = (const float*)d_in[src_idx[i]];
    transpose_all<<<(WT_TOTAL + 255) / 256, 256>>>(ws);

    size_t smem = (size_t)(7 * LSZ + 2 * DD * RP + 520) * sizeof(float);
    cudaFuncSetAttribute(lstm_main, cudaFuncAttributeMaxDynamicSharedMemorySize, (int)smem);

    lstm_main<<<444, NT, smem>>>(enc_x, dec_x,
                                 (const float*)d_in[20], (const float*)d_in[21],
                                 (float*)d_out);
}

// round 10
// speedup vs baseline: 1.7002x; 1.7002x over previous
#include <cuda_runtime.h>

#define TB 8192   // batch
#define TT 512    // seq len
#define DD 8      // input size
#define HH 64     // hidden
#define R  32     // batch rows per block
#define RP 36     // row stride (floats): 144B
#define NT 256    // threads: u = tid&63 (unit), rg = tid>>6 (row group of 8)

// Gate-interleaved transposed weights WTg[k][u][gate] + interleaved biases.
#define WT_TOTAL 185856
__device__ float g_wt[WT_TOTAL];

struct WSrcs { const float* p[18]; };
__constant__ int c_woff[19] = {0, 2048, 18432, 34816, 51200, 67584, 83968,
                               102400, 118784, 135168, 151552, 167936, 184320,
                               184576, 184832, 185088, 185344, 185600, 185856};

__global__ void transpose_all(WSrcs ws) {
    int idx = blockIdx.x * blockDim.x + threadIdx.x;
    if (idx >= WT_TOTAL) return;
    int seg = 0;
    #pragma unroll
    for (int i = 1; i < 18; i++) seg += (idx >= c_woff[i]);
    int off  = c_woff[seg];
    int cols = (c_woff[seg + 1] - off) >> 8;
    int pos = idx - off;
    int k = pos >> 8, rem = pos & 255, u = rem >> 2, g = rem & 3;
    g_wt[idx] = ws.p[seg][(g * HH + u) * cols + k];
}

__device__ __forceinline__ float tanh_fast(float x) {
    float y;
    asm("tanh.approx.f32 %0, %1;" : "=f"(y) : "f"(x));
    return y;
}
__device__ __forceinline__ float sig_fast(float x) {
    return fmaf(0.5f, tanh_fast(0.5f * x), 0.5f);
}

typedef unsigned long long ull;
__device__ __forceinline__ ull pack2(float w) {
    ull p; asm("mov.b64 %0, {%1, %1};" : "=l"(p) : "f"(w)); return p;
}
__device__ __forceinline__ void fma2(ull& acc, ull a, ull b) {
    asm("fma.rn.f32x2 %0, %1, %2, %0;" : "+l"(acc) : "l"(a), "l"(b));
}
__device__ __forceinline__ void unpack2(ull p, float& lo, float& hi) {
    asm("mov.b64 {%0, %1}, %2;" : "=f"(lo), "=f"(hi) : "l"(p));
}

// one k: 4 gate weights (already in regs) x 8 rows (smem broadcast)
__device__ __forceinline__ void do_k(ull acc[16], float4 w4,
                                     const float* __restrict__ xrow) {
    ull wi = pack2(w4.x), wf = pack2(w4.y);
    ull wg = pack2(w4.z), wo = pack2(w4.w);
    const ulonglong2* xp = (const ulonglong2*)xrow;
    ulonglong2 v01 = xp[0];                 // broadcast LDS.128
    ulonglong2 v23 = xp[1];
    fma2(acc[0],  wi, v01.x); fma2(acc[1],  wi, v01.y);
    fma2(acc[2],  wi, v23.x); fma2(acc[3],  wi, v23.y);
    fma2(acc[4],  wf, v01.x); fma2(acc[5],  wf, v01.y);
    fma2(acc[6],  wf, v23.x); fma2(acc[7],  wf, v23.y);
    fma2(acc[8],  wg, v01.x); fma2(acc[9],  wg, v01.y);
    fma2(acc[10], wg, v23.x); fma2(acc[11], wg, v23.y);
    fma2(acc[12], wo, v01.x); fma2(acc[13], wo, v01.y);
    fma2(acc[14], wo, v23.x); fma2(acc[15], wo, v23.y);
}

// gemv with double-buffered weight prefetch (chunk = 4 k). K compile-time.
template<int K>
__device__ __forceinline__ void gemvP(ull acc[16], const float* __restrict__ WTg,
                                      const float* __restrict__ buf,
                                      int u, int rg) {
    const float* wp = WTg + u * 4;
    const float* bp = buf + rg * 8;
    float4 wa[4], wb[4];
    #pragma unroll
    for (int i = 0; i < 4; i++) wa[i] = *(const float4*)(wp + i * 256);
    constexpr int NCH = K / 4;               // 2 or 16, always even
    #pragma unroll 1
    for (int ch = 0; ch < NCH; ch += 2) {
        #pragma unroll
        for (int i = 0; i < 4; i++)          // prefetch chunk ch+1
            wb[i] = *(const float4*)(wp + ((ch + 1) * 4 + i) * 256);
        #pragma unroll
        for (int i = 0; i < 4; i++)          // compute chunk ch
            do_k(acc, wa[i], bp + (ch * 4 + i) * RP);
        if (ch + 2 < NCH) {
            #pragma unroll
            for (int i = 0; i < 4; i++)      // prefetch chunk ch+2
                wa[i] = *(const float4*)(wp + ((ch + 2) * 4 + i) * 256);
        }
        #pragma unroll
        for (int i = 0; i < 4; i++)          // compute chunk ch+1
            do_k(acc, wb[i], bp + ((ch + 1) * 4 + i) * RP);
    }
}

// One LSTM layer step: gemv -> register state update (c in smem, thread-private)
// -> h store -> block sync.
template<int KI, bool HAS2>
__device__ __forceinline__ void layer_step(const float* __restrict__ WTi,
                                           const float* __restrict__ in1,
                                           const float* __restrict__ WTi2,
                                           const float* __restrict__ in2,
                                           const float* __restrict__ WTh,
                                           const float* __restrict__ hprev,
                                           const float* __restrict__ Bint,
                                           float* __restrict__ cbuf,
                                           float* __restrict__ hout,
                                           int u, int rg) {
    ull acc[16];
    {
        float4 b4 = *(const float4*)(Bint + u * 4);
        ull bi = pack2(b4.x), bf = pack2(b4.y), bg = pack2(b4.z), bo = pack2(b4.w);
        acc[0] = acc[1] = acc[2] = acc[3] = bi;
        acc[4] = acc[5] = acc[6] = acc[7] = bf;
        acc[8] = acc[9] = acc[10] = acc[11] = bg;
        acc[12] = acc[13] = acc[14] = acc[15] = bo;
    }
    gemvP<KI>(acc, WTi, in1, u, rg);
    if (HAS2) gemvP<HH>(acc, WTi2, in2, u, rg);
    gemvP<HH>(acc, WTh, hprev, u, rg);

    float* cb = cbuf + u * RP + rg * 8;      // thread-private c slots
    float4 cv0 = *(float4*)cb;
    float4 cv1 = *(float4*)(cb + 4);
    float cc[8] = {cv0.x, cv0.y, cv0.z, cv0.w, cv1.x, cv1.y, cv1.z, cv1.w};
    float hv[8];
    #pragma unroll
    for (int q = 0; q < 4; q++) {
        float i0, i1, f0, f1, g0, g1, o0, o1;
        unpack2(acc[q],      i0, i1);
        unpack2(acc[4 + q],  f0, f1);
        unpack2(acc[8 + q],  g0, g1);
        unpack2(acc[12 + q], o0, o1);
        float c;
        c = cc[2 * q];
        c = sig_fast(f0) * c + sig_fast(i0) * tanh_fast(g0);
        hv[2 * q] = sig_fast(o0) * tanh_fast(c);
        cc[2 * q] = c;
        c = cc[2 * q + 1];
        c = sig_fast(f1) * c + sig_fast(i1) * tanh_fast(g1);
        hv[2 * q + 1] = sig_fast(o1) * tanh_fast(c);
        cc[2 * q + 1] = c;
    }
    *(float4*)cb       = make_float4(cc[0], cc[1], cc[2], cc[3]);
    *(float4*)(cb + 4) = make_float4(cc[4], cc[5], cc[6], cc[7]);
    float4* hp = (float4*)(hout + u * RP + rg * 8);
    hp[0] = make_float4(hv[0], hv[1], hv[2], hv[3]);
    hp[1] = make_float4(hv[4], hv[5], hv[6], hv[7]);
    __syncthreads();
}

#define LSZ (HH * RP)   // 2304 floats

__global__ __launch_bounds__(NT, 2)
void lstm_main(const float* __restrict__ enc_x, const float* __restrict__ dec_x,
               const float* __restrict__ fcW, const float* __restrict__ fcb,
               float* __restrict__ out) {
    extern __shared__ float sm[];
    float* s_h  = sm;                     // [2 parity][3 layer][64][RP]
    float* s_c  = sm + 6 * LSZ;           // [3 layer][64][RP]
    float* s_x  = sm + 9 * LSZ;           // [2 parity][8][RP]
    float* s_fc = s_x + 2 * DD * RP;      // 512 fcW^T + 8 fcb

    int tid = threadIdx.x;
    int b0  = blockIdx.x * R;
    int u = tid & 63, rg = tid >> 6;      // gemv tile coords
    int xr = tid >> 3, xk = tid & 7;      // x staging coords
    int pr = tid >> 3, pd = tid & 7;      // fc output coords

    for (int i = tid; i < 9 * LSZ; i += NT) sm[i] = 0.f;
    for (int i = tid; i < DD * HH; i += NT) {
        int uu = i >> 3, d = i & 7;
        s_fc[uu * 8 + d] = fcW[d * HH + uu];
    }
    if (tid < DD) s_fc[512 + tid] = fcb[tid];

    const float* WT_e0i = g_wt;           const float* WT_e0h = g_wt + 2048;
    const float* WT_e1i = g_wt + 18432;   const float* WT_e1h = g_wt + 34816;
    const float* WT_e2i = g_wt + 51200;   const float* WT_e2h = g_wt + 67584;
    const float* WT_d0i = g_wt + 83968;   const float* WT_d0h = g_wt + 102400;
    const float* WT_d1i = g_wt + 118784;  const float* WT_d1h = g_wt + 135168;
    const float* WT_d2i = g_wt + 151552;  const float* WT_d2h = g_wt + 167936;
    const float* B_e0 = g_wt + 184320;    const float* B_e1 = g_wt + 184576;
    const float* B_e2 = g_wt + 184832;    const float* B_d0 = g_wt + 185088;
    const float* B_d1 = g_wt + 185344;    const float* B_d2 = g_wt + 185600;

    const size_t xbase = (size_t)(b0 + xr) * TT * DD + xk;

    // prologue: x(t=0) into parity 0 (init zeros + x ordered by this sync)
    s_x[xk * RP + xr] = enc_x[xbase];
    __syncthreads();

    // ---------------- encoder ----------------
    for (int t = 0; t < TT; t++) {
        int p = t & 1;
        float* hc = s_h + p * 3 * LSZ;          // write parity
        float* hv = s_h + (p ^ 1) * 3 * LSZ;    // read parity
        const float* sx = s_x + p * DD * RP;
        float xn = (t < TT - 1) ? enc_x[xbase + (size_t)(t + 1) * DD]
                                : dec_x[xbase];
        layer_step<DD, false>(WT_e0i, sx, nullptr, nullptr, WT_e0h, hv,
                              B_e0, s_c, hc, u, rg);
        layer_step<HH, false>(WT_e1i, hc, nullptr, nullptr, WT_e1h, hv + LSZ,
                              B_e1, s_c + LSZ, hc + LSZ, u, rg);
        s_x[(p ^ 1) * DD * RP + xk * RP + xr] = xn;   // ordered by L2's sync
        layer_step<HH, false>(WT_e2i, hc + LSZ, nullptr, nullptr, WT_e2h, hv + 2 * LSZ,
                              B_e2, s_c + 2 * LSZ, hc + 2 * LSZ, u, rg);
    }

    // ---------------- decoder ----------------
    for (int t = 0; t < TT; t++) {
        int p = t & 1;
        float* hc = s_h + p * 3 * LSZ;
        float* hv = s_h + (p ^ 1) * 3 * LSZ;
        const float* sx = s_x + p * DD * RP;
        int tn = (t + 1 < TT) ? t + 1 : t;
        float xn = dec_x[xbase + (size_t)tn * DD];
        const float* ybuf = hv + 2 * LSZ;             // y_prev = prev-parity h2
        if (t > 0)
            layer_step<DD, true>(WT_d0i, sx, WT_d0i + DD * 256, ybuf, WT_d0h, hv,
                                 B_d0, s_c, hc, u, rg);
        else
            layer_step<DD, false>(WT_d0i, sx, nullptr, nullptr, WT_d0h, hv,
                                  B_d0, s_c, hc, u, rg);
        layer_step<HH, false>(WT_d1i, hc, nullptr, nullptr, WT_d1h, hv + LSZ,
                              B_d1, s_c + LSZ, hc + LSZ, u, rg);
        s_x[(p ^ 1) * DD * RP + xk * RP + xr] = xn;
        layer_step<HH, false>(WT_d2i, hc + LSZ, nullptr, nullptr, WT_d2h, hv + 2 * LSZ,
                              B_d2, s_c + 2 * LSZ, hc + 2 * LSZ, u, rg);

        // pred = h2 @ fcW^T + fcb (ordered by L2's sync)
        const float* h2 = hc + 2 * LSZ;
        float a = s_fc[512 + pd];
        #pragma unroll 8
        for (int uu = 0; uu < HH; uu++)
            a = fmaf(s_fc[uu * 8 + pd], h2[uu * RP + pr], a);
        out[(size_t)(b0 + pr) * TT * DD + t * DD + pd] = a;
    }
}

extern "C" void kernel_launch(void* const* d_in, const int* in_sizes, int n_in,
                              void* d_out, int out_size) {
    const float* enc_x = (const float*)d_in[0];
    const float* dec_x = (const float*)d_in[1];

    WSrcs ws;
    const int src_idx[18] = {2, 3, 5, 6, 8, 9, 11, 12, 14, 15, 17, 18,
                             4, 7, 10, 13, 16, 19};
    for (int i = 0; i < 18; i++) ws.p[i] = (const float*)d_in[src_idx[i]];
    transpose_all<<<(WT_TOTAL + 255) / 256, 256>>>(ws);

    size_t smem = (size_t)(9 * LSZ + 2 * DD * RP + 520) * sizeof(float);
    cudaFuncSetAttribute(lstm_main, cudaFuncAttributeMaxDynamicSharedMemorySize, (int)smem);

    lstm_main<<<TB / R, NT, smem>>>(enc_x, dec_x,
                                    (const float*)d_in[20], (const float*)d_in[21],
                                    (float*)d_out);
}